// round 2
// baseline (speedup 1.0000x reference)
#include <cuda_runtime.h>
#include <cuda_bf16.h>

#define N_NODES 100000
#define N_EDGES 1600000
#define IN_CH   128
#define OUT_CH  64

// ---------------- device scratch (static, allocation-free) ----------------
__device__ float g_Wtmp[IN_CH * IN_CH];     // W1@W2  [128,128]
__device__ float g_Wc[IN_CH * OUT_CH];      // W1@W2@W3 [128,64]
__device__ int   g_src[N_EDGES];
__device__ int   g_dst[N_EDGES];
__device__ int   g_col[N_EDGES];            // src ids grouped by dst (CSR cols)
__device__ int   g_off[N_NODES + 1];        // CSR row offsets
__device__ int   g_cnt[N_NODES];            // histogram, then cursor
__device__ int   g_bsum[256];               // scan block partials
__device__ float g_t[N_NODES * OUT_CH];     // ping
__device__ float g_y[N_NODES * OUT_CH];     // pong
__device__ int   g_is64;

// ---------------- dtype detection ----------------
__global__ void k_detect(const int* ei) {
    if (threadIdx.x == 0 && blockIdx.x == 0) {
        int is64 = 1;
        for (int i = 0; i < 64; i++) {
            if (ei[2 * i + 1] != 0) { is64 = 0; break; }
        }
        g_is64 = is64;
    }
}

// ---------------- convert edge_index -> int32, zero histogram ----------------
__global__ void k_convert(const void* ei) {
    int is64 = g_is64;
    int tid = blockIdx.x * blockDim.x + threadIdx.x;
    int stride = gridDim.x * blockDim.x;
    for (int e = tid; e < N_EDGES; e += stride) {
        int s, d;
        if (is64) {
            const long long* p = (const long long*)ei;
            s = (int)p[e];
            d = (int)p[(long long)N_EDGES + e];
        } else {
            const int* p = (const int*)ei;
            s = p[e];
            d = p[N_EDGES + e];
        }
        g_src[e] = s;
        g_dst[e] = d;
    }
    for (int i = tid; i < N_NODES; i += stride) g_cnt[i] = 0;
}

__global__ void k_hist() {
    int e = blockIdx.x * blockDim.x + threadIdx.x;
    if (e < N_EDGES) atomicAdd(&g_cnt[g_dst[e]], 1);
}

// ---------------- exclusive scan (3 kernels) ----------------
#define SCAN_T 512
__global__ void k_scan1() {
    __shared__ int s[SCAN_T];
    int t = threadIdx.x;
    int idx = blockIdx.x * SCAN_T + t;
    int v = (idx < N_NODES) ? g_cnt[idx] : 0;
    s[t] = v;
    __syncthreads();
    for (int o = 1; o < SCAN_T; o <<= 1) {
        int add = (t >= o) ? s[t - o] : 0;
        __syncthreads();
        s[t] += add;
        __syncthreads();
    }
    if (idx < N_NODES) g_off[idx] = s[t] - v;   // exclusive (local)
    if (t == SCAN_T - 1) g_bsum[blockIdx.x] = s[t];
}
__global__ void k_scan2(int nblocks) {
    if (threadIdx.x == 0 && blockIdx.x == 0) {
        int run = 0;
        for (int i = 0; i < nblocks; i++) {
            int v = g_bsum[i];
            g_bsum[i] = run;
            run += v;
        }
    }
}
__global__ void k_scan3() {
    int idx = blockIdx.x * SCAN_T + threadIdx.x;
    if (idx < N_NODES) g_off[idx] += g_bsum[blockIdx.x];
    if (idx == 0) g_off[N_NODES] = N_EDGES;
}

__global__ void k_initcur() {
    int idx = blockIdx.x * SCAN_T + threadIdx.x;
    if (idx < N_NODES) g_cnt[idx] = g_off[idx];
}

__global__ void k_fill() {
    int e = blockIdx.x * blockDim.x + threadIdx.x;
    if (e < N_EDGES) {
        int d = g_dst[e];
        int p = atomicAdd(&g_cnt[d], 1);
        g_col[p] = g_src[e];
    }
}

// ---------------- weight chain: Wtmp = W1@W2 ; Wc = Wtmp@W3 ----------------
__global__ void k_w1w2(const float* __restrict__ W1, const float* __restrict__ W2) {
    int k = blockIdx.x;      // 0..127
    int j = threadIdx.x;     // 0..127
    float s = 0.f;
#pragma unroll 8
    for (int m = 0; m < IN_CH; m++)
        s += W1[k * IN_CH + m] * W2[m * IN_CH + j];
    g_Wtmp[k * IN_CH + j] = s;
}
__global__ void k_wc(const float* __restrict__ W3) {
    int k = blockIdx.x;      // 0..127
    int j = threadIdx.x;     // 0..63
    float s = 0.f;
#pragma unroll 8
    for (int m = 0; m < IN_CH; m++)
        s += g_Wtmp[k * IN_CH + m] * W3[m * OUT_CH + j];
    g_Wc[k * OUT_CH + j] = s;
}

// ---------------- GEMM: t[100000,64] = x[100000,128] @ Wc[128,64] ----------------
// block tile M=64, N=64 (all cols), K chunks of 64; 256 threads, 4x4 per thread
#define GM 64
#define GK 64
__global__ __launch_bounds__(256) void k_gemm(const float* __restrict__ x) {
    __shared__ float XsT[GK][GM + 4];   // transposed: [k][row]
    __shared__ float Ws[GK][OUT_CH];    // [k][col]
    int row0 = blockIdx.x * GM;
    int tid = threadIdx.x;
    int ty = tid >> 4;        // 0..15 -> rows ty*4..+3
    int tx = tid & 15;        // 0..15 -> cols tx*4..+3
    float acc[4][4];
#pragma unroll
    for (int i = 0; i < 4; i++)
#pragma unroll
        for (int j = 0; j < 4; j++) acc[i][j] = 0.f;

    for (int kc = 0; kc < IN_CH; kc += GK) {
        // load X tile (64 rows x 64 k) transposed
#pragma unroll
        for (int i = 0; i < 4; i++) {
            int slot = tid + i * 256;           // 0..1023 float4 slots
            int r = slot >> 4;                  // row 0..63
            int kq = slot & 15;                 // float4 idx within 64 k
            int grow = row0 + r;
            float4 v = make_float4(0.f, 0.f, 0.f, 0.f);
            if (grow < N_NODES)
                v = *(const float4*)&x[(long long)grow * IN_CH + kc + kq * 4];
            XsT[kq * 4 + 0][r] = v.x;
            XsT[kq * 4 + 1][r] = v.y;
            XsT[kq * 4 + 2][r] = v.z;
            XsT[kq * 4 + 3][r] = v.w;
        }
        // load W tile (64 k x 64 n)
#pragma unroll
        for (int i = 0; i < 4; i++) {
            int slot = tid + i * 256;
            int k = slot >> 4;
            int nq = slot & 15;
            *(float4*)&Ws[k][nq * 4] =
                *(const float4*)&g_Wc[(kc + k) * OUT_CH + nq * 4];
        }
        __syncthreads();
#pragma unroll
        for (int k = 0; k < GK; k++) {
            float4 a = *(const float4*)&XsT[k][ty * 4];
            float4 b = *(const float4*)&Ws[k][tx * 4];
            float ar[4] = {a.x, a.y, a.z, a.w};
            float br[4] = {b.x, b.y, b.z, b.w};
#pragma unroll
            for (int i = 0; i < 4; i++)
#pragma unroll
                for (int j = 0; j < 4; j++) acc[i][j] += ar[i] * br[j];
        }
        __syncthreads();
    }
#pragma unroll
    for (int i = 0; i < 4; i++) {
        int grow = row0 + ty * 4 + i;
        if (grow < N_NODES) {
            float4 o = make_float4(acc[i][0], acc[i][1], acc[i][2], acc[i][3]);
            *(float4*)&g_t[(long long)grow * OUT_CH + tx * 4] = o;
        }
    }
}

// ---------------- CSR aggregation: out[n] = sum_{e in row n} in[col[e]] ----------------
// phase 0: g_t -> g_y ; phase 1: g_y -> g_t ; phase 2: g_t -> out_final
// Pointers to __device__ globals are resolved IN DEVICE CODE (host-side symbol
// references are invalid device pointers — that was the R1 bug).
__global__ __launch_bounds__(256) void k_agg(int phase, float* __restrict__ out_final) {
    const float* __restrict__ in = (phase == 1) ? g_y : g_t;
    float* __restrict__ out = (phase == 0) ? g_y : (phase == 1) ? g_t : out_final;

    int tid = blockIdx.x * blockDim.x + threadIdx.x;
    int node = tid >> 4;
    int l = tid & 15;
    if (node >= N_NODES) return;
    int s = g_off[node];
    int e = g_off[node + 1];
    float4 acc = make_float4(0.f, 0.f, 0.f, 0.f);
    int i = s;
    for (; i + 2 <= e; i += 2) {
        int c0 = __ldg(&g_col[i]);
        int c1 = __ldg(&g_col[i + 1]);
        float4 v0 = *(const float4*)&in[c0 * OUT_CH + l * 4];
        float4 v1 = *(const float4*)&in[c1 * OUT_CH + l * 4];
        acc.x += v0.x + v1.x;
        acc.y += v0.y + v1.y;
        acc.z += v0.z + v1.z;
        acc.w += v0.w + v1.w;
    }
    if (i < e) {
        int c = __ldg(&g_col[i]);
        float4 v = *(const float4*)&in[c * OUT_CH + l * 4];
        acc.x += v.x; acc.y += v.y; acc.z += v.z; acc.w += v.w;
    }
    *(float4*)&out[node * OUT_CH + l * 4] = acc;
}

// ---------------- launch ----------------
extern "C" void kernel_launch(void* const* d_in, const int* in_sizes, int n_in,
                              void* d_out, int out_size) {
    const float* x  = (const float*)d_in[0];
    const void*  ei = d_in[1];
    const float* W1 = (const float*)d_in[2];
    const float* W2 = (const float*)d_in[3];
    const float* W3 = (const float*)d_in[4];
    float* out = (float*)d_out;

    const int EB = (N_EDGES + 255) / 256;            // 6250
    const int SB = (N_NODES + SCAN_T - 1) / SCAN_T;  // 196
    const int GB = (N_NODES + GM - 1) / GM;          // 1563
    const int AB = (N_NODES * 16 + 255) / 256;       // 6250

    k_detect<<<1, 32>>>((const int*)ei);
    k_convert<<<2048, 256>>>(ei);
    k_hist<<<EB, 256>>>();
    k_scan1<<<SB, SCAN_T>>>();
    k_scan2<<<1, 32>>>(SB);
    k_scan3<<<SB, SCAN_T>>>();
    k_initcur<<<SB, SCAN_T>>>();
    k_fill<<<EB, 256>>>();

    k_w1w2<<<IN_CH, IN_CH>>>(W1, W2);
    k_wc<<<IN_CH, OUT_CH>>>(W3);
    k_gemm<<<GB, 256>>>(x);

    k_agg<<<AB, 256>>>(0, out);
    k_agg<<<AB, 256>>>(1, out);
    k_agg<<<AB, 256>>>(2, out);
}